// round 12
// baseline (speedup 1.0000x reference)
#include <cuda_runtime.h>
#include <cstdint>

#define B 8
#define DIM 192
#define Hh 128
#define Ww 128
#define KS 7
#define PAD 3
#define HID 48
#define KK 49          // 7*7
#define PLANE (Hh*Ww)  // 16384
#define OUTW (DIM*KK)  // 9408
#define EPS 1e-5f

// -------- scratch (device globals; no allocation allowed) --------
__device__ float g_pooled[B * DIM];      // [b, c]
__device__ float g_wdyn[B * OUTW];       // [b, c*49 + k]

// -------- cp.async helpers --------
__device__ __forceinline__ void cp_async4(uint32_t saddr, const void* g, bool ok) {
    int sz = ok ? 4 : 0;
    asm volatile("cp.async.ca.shared.global [%0], [%1], 4, %2;"
                 :: "r"(saddr), "l"(g), "r"(sz));
}
__device__ __forceinline__ void cp_async16(uint32_t saddr, const void* g, bool ok) {
    int sz = ok ? 16 : 0;
    asm volatile("cp.async.cg.shared.global [%0], [%1], 16, %2;"
                 :: "r"(saddr), "l"(g), "r"(sz));
}
__device__ __forceinline__ void cp_commit() {
    asm volatile("cp.async.commit_group;");
}
__device__ __forceinline__ void cp_wait_all() {
    asm volatile("cp.async.wait_group 0;");
}
__device__ __forceinline__ uint32_t smem_u32(const void* p) {
    return (uint32_t)__cvta_generic_to_shared(p);
}

// ============================================================
// Kernel 1: global average pool over HxW per (b,c) plane
// ============================================================
__global__ __launch_bounds__(256) void pool_kernel(const float* __restrict__ x) {
    int bc = blockIdx.x;
    const float4* p = reinterpret_cast<const float4*>(x + (size_t)bc * PLANE);
    float s = 0.f;
    #pragma unroll 4
    for (int i = threadIdx.x; i < PLANE / 4; i += 256) {
        float4 v = p[i];
        s += (v.x + v.y) + (v.z + v.w);
    }
    #pragma unroll
    for (int off = 16; off > 0; off >>= 1)
        s += __shfl_down_sync(0xffffffffu, s, off);
    __shared__ float red[8];
    int lane = threadIdx.x & 31, warp = threadIdx.x >> 5;
    if (lane == 0) red[warp] = s;
    __syncthreads();
    if (warp == 0) {
        float t = (lane < 8) ? red[lane] : 0.f;
        #pragma unroll
        for (int off = 4; off > 0; off >>= 1)
            t += __shfl_down_sync(0xffffffffu, t, off);
        if (lane == 0) g_pooled[bc] = t * (1.0f / (float)PLANE);
    }
}

// ============================================================
// Kernel 2 (fused): y = relu(BN(pooled @ w1^T)) per block, then
// wdyn[b, o] = y . w2[o,:] + b2[o] for a 128-wide chunk of o.
// ============================================================
#define W2_CHUNK 128
__global__ __launch_bounds__(128) void gen_wdyn_kernel(
    const float* __restrict__ w1,
    const float* __restrict__ gamma, const float* __restrict__ beta,
    const float* __restrict__ mean,  const float* __restrict__ var,
    const float* __restrict__ w2, const float* __restrict__ b2) {
    int b = blockIdx.y;
    int obase = blockIdx.x * W2_CHUNK;
    int t = threadIdx.x;

    __shared__ float sy[HID];
    __shared__ float w2s[W2_CHUNK * (HID + 1)];

    if (t < HID) {
        const float* pr = g_pooled + b * DIM;
        const float* wr = w1 + t * DIM;
        float s = 0.f;
        #pragma unroll 8
        for (int c = 0; c < DIM; c++) s = fmaf(pr[c], wr[c], s);
        s = (s - mean[t]) * rsqrtf(var[t] + EPS) * gamma[t] + beta[t];
        sy[t] = s > 0.f ? s : 0.f;
    }

    const int n_f4 = W2_CHUNK * HID / 4;
    const float4* w2v = reinterpret_cast<const float4*>(w2 + (size_t)obase * HID);
    int max_f4 = (OUTW - obase) * HID / 4;
    for (int i = t; i < n_f4; i += 128) {
        float4 v = (i < max_f4) ? w2v[i] : make_float4(0.f, 0.f, 0.f, 0.f);
        int row = i / (HID / 4);
        int col = (i % (HID / 4)) * 4;
        float* dst = &w2s[row * (HID + 1) + col];
        dst[0] = v.x; dst[1] = v.y; dst[2] = v.z; dst[3] = v.w;
    }
    __syncthreads();

    int o = obase + t;
    if (o < OUTW) {
        float acc = b2[o];
        const float* wr = &w2s[t * (HID + 1)];
        #pragma unroll
        for (int h = 0; h < HID; h++) acc = fmaf(sy[h], wr[h], acc);
        g_wdyn[(size_t)b * OUTW + o] = acc;
    }
}

// ============================================================
// Kernel 3: persistent double-buffered depthwise 7x7 conv + bias.
// 456 blocks (3/SM). kh-split two-pass compute keeps peak registers
// ~70 so (256,3) fits without spills: pass A holds 28 weights
// (kh 0-3, tile rows 0-6), pass B holds 21 (kh 4-6, rows 4-9).
// Tile layout as R10: gc=g at smem col g+4 (stride 136); halo cols
// zeroed once; 16B cp.async streams the 128 main floats/row.
// ============================================================
#define STRIP 32
#define TROWS (STRIP + KS - 1)   // 38
#define TSTRIDE 136              // 544B row stride
#define COLOFF 4                 // smem col of gc=0
#define NTILES (B * DIM * (Hh / STRIP))   // 6144
#define DW_GRID 456
#define NCHUNK (TROWS * 32)      // 1216 16B chunks per tile

__device__ __forceinline__ void load_tile_async(
    float* tbuf, float* wbuf, int tile, const float* __restrict__ x) {
    int bc = tile >> 2;
    int strip = tile & 3;
    int r0 = strip * STRIP;
    int tid = threadIdx.x;

    if (tid < KK)
        cp_async4(smem_u32(wbuf + tid), &g_wdyn[(size_t)bc * KK + tid], true);

    const float* plane = x + (size_t)bc * PLANE;
    #pragma unroll
    for (int i = 0; i < 5; i++) {
        int idx = tid + i * 256;
        if (idx < NCHUNK) {
            int rr = idx >> 5;          // tile row
            int ch = idx & 31;          // 16B chunk within row
            int gr = r0 + rr - PAD;
            bool ok = (gr >= 0) && (gr < Hh);
            const float* src = ok ? (plane + (size_t)gr * Ww + ch * 4) : plane;
            cp_async16(smem_u32(tbuf + rr * TSTRIDE + COLOFF + ch * 4), src, ok);
        }
    }
}

__global__ __launch_bounds__(256, 3) void dwconv_kernel(
    const float* __restrict__ x, const float* __restrict__ bias,
    float* __restrict__ out) {
    __shared__ __align__(16) float tbuf[2][TROWS * TSTRIDE];
    __shared__ __align__(16) float wbuf[2][52];

    int tid = threadIdx.x;
    int cg = tid & 31, rg = tid >> 5;
    int col = cg * 4;
    int rbase = rg * 4;
    const int grid = gridDim.x;

    // zero the permanent halo columns of both buffers (once)
    for (int i = tid; i < 2 * TROWS * 8; i += 256) {
        int bufi = i >= TROWS * 8;
        int j = i - bufi * TROWS * 8;
        int rr = j >> 3;
        int k = j & 7;
        int cc = (k < 4) ? k : (128 + COLOFF + (k - 4));
        tbuf[bufi][rr * TSTRIDE + cc] = 0.f;
    }

    int t = blockIdx.x;
    if (t < NTILES) {
        load_tile_async(tbuf[0], wbuf[0], t, x);
        cp_commit();
    }
    int cur = 0;

    for (; t < NTILES; t += grid) {
        cp_wait_all();
        __syncthreads();

        int tn = t + grid;
        if (tn < NTILES) {
            load_tile_async(tbuf[cur ^ 1], wbuf[cur ^ 1], tn, x);
            cp_commit();
        }

        int bc = t >> 2;
        int r0 = (t & 3) * STRIP;

        float bia = __ldg(&bias[bc % DIM]);
        float acc[4][4];
        #pragma unroll
        for (int i = 0; i < 4; i++)
            #pragma unroll
            for (int j = 0; j < 4; j++) acc[i][j] = bia;

        const float* tile = tbuf[cur];
        const float* wsm = wbuf[cur];

        // ---- pass A: kh 0..3 (28 weights in regs), tile rows 0..6 ----
        {
            float w[28];
            const float4* wv = reinterpret_cast<const float4*>(wsm);
            #pragma unroll
            for (int q = 0; q < 7; q++) {
                float4 f = wv[q];
                w[4 * q] = f.x; w[4 * q + 1] = f.y;
                w[4 * q + 2] = f.z; w[4 * q + 3] = f.w;
            }
            #pragma unroll
            for (int ir = 0; ir < 7; ir++) {
                const float* tr = &tile[(rbase + ir) * TSTRIDE + col];
                float4 A = *reinterpret_cast<const float4*>(tr);
                float4 Bv = *reinterpret_cast<const float4*>(tr + 4);
                float4 Cv = *reinterpret_cast<const float4*>(tr + 8);
                float v[12] = {A.x, A.y, A.z, A.w,
                               Bv.x, Bv.y, Bv.z, Bv.w,
                               Cv.x, Cv.y, Cv.z, Cv.w};
                #pragma unroll
                for (int kh = 0; kh < 4; kh++) {
                    int orr = ir - kh;
                    if (orr >= 0 && orr < 4) {
                        #pragma unroll
                        for (int jj = 0; jj < 4; jj++) {
                            float s = acc[orr][jj];
                            #pragma unroll
                            for (int kw = 0; kw < KS; kw++)
                                s = fmaf(v[jj + kw + 1], w[kh * KS + kw], s);
                            acc[orr][jj] = s;
                        }
                    }
                }
            }
        }

        // ---- pass B: kh 4..6 (21 weights in regs), tile rows 4..9 ----
        {
            float w[21];
            #pragma unroll
            for (int q = 0; q < 21; q++) w[q] = wsm[28 + q];
            #pragma unroll
            for (int ir = 4; ir < 10; ir++) {
                const float* tr = &tile[(rbase + ir) * TSTRIDE + col];
                float4 A = *reinterpret_cast<const float4*>(tr);
                float4 Bv = *reinterpret_cast<const float4*>(tr + 4);
                float4 Cv = *reinterpret_cast<const float4*>(tr + 8);
                float v[12] = {A.x, A.y, A.z, A.w,
                               Bv.x, Bv.y, Bv.z, Bv.w,
                               Cv.x, Cv.y, Cv.z, Cv.w};
                #pragma unroll
                for (int kh = 4; kh < 7; kh++) {
                    int orr = ir - kh;
                    if (orr >= 0 && orr < 4) {
                        #pragma unroll
                        for (int jj = 0; jj < 4; jj++) {
                            float s = acc[orr][jj];
                            #pragma unroll
                            for (int kw = 0; kw < KS; kw++)
                                s = fmaf(v[jj + kw + 1], w[(kh - 4) * KS + kw], s);
                            acc[orr][jj] = s;
                        }
                    }
                }
            }
        }

        float* op = out + (size_t)bc * PLANE + (size_t)(r0 + rbase) * Ww + col;
        #pragma unroll
        for (int orr = 0; orr < 4; orr++)
            *reinterpret_cast<float4*>(op + (size_t)orr * Ww) =
                make_float4(acc[orr][0], acc[orr][1], acc[orr][2], acc[orr][3]);

        cur ^= 1;
    }
}

// ============================================================
// launch
// inputs: 0:x 1:w1 2:bn_gamma 3:bn_beta 4:bn_mean 5:bn_var 6:w2 7:b2 8:bias
// ============================================================
extern "C" void kernel_launch(void* const* d_in, const int* in_sizes, int n_in,
                              void* d_out, int out_size) {
    const float* x     = (const float*)d_in[0];
    const float* w1    = (const float*)d_in[1];
    const float* gamma = (const float*)d_in[2];
    const float* beta  = (const float*)d_in[3];
    const float* mean  = (const float*)d_in[4];
    const float* var   = (const float*)d_in[5];
    const float* w2    = (const float*)d_in[6];
    const float* b2    = (const float*)d_in[7];
    const float* bias  = (const float*)d_in[8];
    float* out = (float*)d_out;

    pool_kernel<<<B * DIM, 256>>>(x);
    dim3 g2((OUTW + W2_CHUNK - 1) / W2_CHUNK, B);
    gen_wdyn_kernel<<<g2, 128>>>(w1, gamma, beta, mean, var, w2, b2);
    dwconv_kernel<<<DW_GRID, 256>>>(x, bias, out);
}

// round 14
// speedup vs baseline: 1.4250x; 1.4250x over previous
#include <cuda_runtime.h>
#include <cstdint>

#define B 8
#define DIM 192
#define Hh 128
#define Ww 128
#define KS 7
#define PAD 3
#define HID 48
#define KK 49          // 7*7
#define PLANE (Hh*Ww)  // 16384
#define OUTW (DIM*KK)  // 9408
#define EPS 1e-5f

// -------- scratch (device globals; no allocation allowed) --------
__device__ float g_pooled[B * DIM];      // [b, c]
__device__ float g_wdyn[B * OUTW];       // [b, c*49 + k]
__device__ int   g_tile_counter;         // dynamic dwconv tile cursor

// -------- cp.async helpers --------
__device__ __forceinline__ void cp_async4(uint32_t saddr, const void* g, bool ok) {
    int sz = ok ? 4 : 0;
    asm volatile("cp.async.ca.shared.global [%0], [%1], 4, %2;"
                 :: "r"(saddr), "l"(g), "r"(sz));
}
__device__ __forceinline__ void cp_async16(uint32_t saddr, const void* g, bool ok) {
    int sz = ok ? 16 : 0;
    asm volatile("cp.async.cg.shared.global [%0], [%1], 16, %2;"
                 :: "r"(saddr), "l"(g), "r"(sz));
}
__device__ __forceinline__ void cp_commit() {
    asm volatile("cp.async.commit_group;");
}
__device__ __forceinline__ void cp_wait_all() {
    asm volatile("cp.async.wait_group 0;");
}
__device__ __forceinline__ uint32_t smem_u32(const void* p) {
    return (uint32_t)__cvta_generic_to_shared(p);
}

// ============================================================
// Kernel 1: global average pool; 16 fully-unrolled independent
// LDG.128 per thread (MLP=16), 4 accumulators.
// ============================================================
__global__ __launch_bounds__(256) void pool_kernel(const float* __restrict__ x) {
    int bc = blockIdx.x;
    const float4* p = reinterpret_cast<const float4*>(x + (size_t)bc * PLANE);
    float s0 = 0.f, s1 = 0.f, s2 = 0.f, s3 = 0.f;
    #pragma unroll
    for (int k = 0; k < 16; k++) {
        float4 v = p[threadIdx.x + k * 256];
        s0 += v.x; s1 += v.y; s2 += v.z; s3 += v.w;
    }
    float s = (s0 + s1) + (s2 + s3);
    #pragma unroll
    for (int off = 16; off > 0; off >>= 1)
        s += __shfl_down_sync(0xffffffffu, s, off);
    __shared__ float red[8];
    int lane = threadIdx.x & 31, warp = threadIdx.x >> 5;
    if (lane == 0) red[warp] = s;
    __syncthreads();
    if (warp == 0) {
        float t = (lane < 8) ? red[lane] : 0.f;
        #pragma unroll
        for (int off = 4; off > 0; off >>= 1)
            t += __shfl_down_sync(0xffffffffu, t, off);
        if (lane == 0) g_pooled[bc] = t * (1.0f / (float)PLANE);
    }
}

// ============================================================
// Kernel 2 (fused): y = relu(BN(pooled @ w1^T)) per block, then
// wdyn[b, o] = y . w2[o,:] + b2[o]. Also resets the dwconv tile
// counter each launch (stream-ordered before dwconv).
// ============================================================
#define W2_CHUNK 128
#define DW_GRID 304
__global__ __launch_bounds__(128) void gen_wdyn_kernel(
    const float* __restrict__ w1,
    const float* __restrict__ gamma, const float* __restrict__ beta,
    const float* __restrict__ mean,  const float* __restrict__ var,
    const float* __restrict__ w2, const float* __restrict__ b2) {
    int b = blockIdx.y;
    int obase = blockIdx.x * W2_CHUNK;
    int t = threadIdx.x;

    if (blockIdx.x == 0 && blockIdx.y == 0 && t == 0)
        g_tile_counter = DW_GRID;        // reset for this launch's dwconv

    __shared__ float sy[HID];
    __shared__ float w2s[W2_CHUNK * (HID + 1)];

    if (t < HID) {
        const float* pr = g_pooled + b * DIM;
        const float* wr = w1 + t * DIM;
        float s = 0.f;
        #pragma unroll 8
        for (int c = 0; c < DIM; c++) s = fmaf(pr[c], wr[c], s);
        s = (s - mean[t]) * rsqrtf(var[t] + EPS) * gamma[t] + beta[t];
        sy[t] = s > 0.f ? s : 0.f;
    }

    const int n_f4 = W2_CHUNK * HID / 4;
    const float4* w2v = reinterpret_cast<const float4*>(w2 + (size_t)obase * HID);
    int max_f4 = (OUTW - obase) * HID / 4;
    for (int i = t; i < n_f4; i += 128) {
        float4 v = (i < max_f4) ? w2v[i] : make_float4(0.f, 0.f, 0.f, 0.f);
        int row = i / (HID / 4);
        int col = (i % (HID / 4)) * 4;
        float* dst = &w2s[row * (HID + 1) + col];
        dst[0] = v.x; dst[1] = v.y; dst[2] = v.z; dst[3] = v.w;
    }
    __syncthreads();

    int o = obase + t;
    if (o < OUTW) {
        float acc = b2[o];
        const float* wr = &w2s[t * (HID + 1)];
        #pragma unroll
        for (int h = 0; h < HID; h++) acc = fmaf(sy[h], wr[h], acc);
        g_wdyn[(size_t)b * OUTW + o] = acc;
    }
}

// ============================================================
// Kernel 3: persistent double-buffered depthwise 7x7 conv + bias.
// R10 compute shape (4x4 patch, 49 weights in regs, (256,2)).
// Tiles claimed via atomic counter; next-tile index ping-pong
// broadcast through s_next[cur] (written during compute of the
// previous tile, made visible by the existing loop-top barrier).
// ============================================================
#define STRIP 32
#define TROWS (STRIP + KS - 1)   // 38
#define TSTRIDE 136              // 544B row stride
#define COLOFF 4                 // smem col of gc=0
#define NTILES (B * DIM * (Hh / STRIP))   // 6144
#define NCHUNK (TROWS * 32)      // 1216 16B chunks per tile

__device__ __forceinline__ void load_tile_async(
    float* tbuf, float* wbuf, int tile, const float* __restrict__ x) {
    int bc = tile >> 2;
    int strip = tile & 3;
    int r0 = strip * STRIP;
    int tid = threadIdx.x;

    if (tid < KK)
        cp_async4(smem_u32(wbuf + tid), &g_wdyn[(size_t)bc * KK + tid], true);

    const float* plane = x + (size_t)bc * PLANE;
    #pragma unroll
    for (int i = 0; i < 5; i++) {
        int idx = tid + i * 256;
        if (idx < NCHUNK) {
            int rr = idx >> 5;          // tile row
            int ch = idx & 31;          // 16B chunk within row
            int gr = r0 + rr - PAD;
            bool ok = (gr >= 0) && (gr < Hh);
            const float* src = ok ? (plane + (size_t)gr * Ww + ch * 4) : plane;
            cp_async16(smem_u32(tbuf + rr * TSTRIDE + COLOFF + ch * 4), src, ok);
        }
    }
}

__global__ __launch_bounds__(256, 2) void dwconv_kernel(
    const float* __restrict__ x, const float* __restrict__ bias,
    float* __restrict__ out) {
    __shared__ __align__(16) float tbuf[2][TROWS * TSTRIDE];
    __shared__ __align__(16) float wbuf[2][52];
    __shared__ int s_next[2];

    int tid = threadIdx.x;
    int cg = tid & 31, rg = tid >> 5;
    int col = cg * 4;
    int rbase = rg * 4;

    // zero the permanent halo columns of both buffers (once)
    for (int i = tid; i < 2 * TROWS * 8; i += 256) {
        int bufi = i >= TROWS * 8;
        int j = i - bufi * TROWS * 8;
        int rr = j >> 3;
        int k = j & 7;
        int cc = (k < 4) ? k : (128 + COLOFF + (k - 4));
        tbuf[bufi][rr * TSTRIDE + cc] = 0.f;
    }

    int t = blockIdx.x;                 // first tile: static assignment
    if (t < NTILES) {
        load_tile_async(tbuf[0], wbuf[0], t, x);
        cp_commit();
    }
    if (tid == 0) s_next[0] = atomicAdd(&g_tile_counter, 1);
    int cur = 0;

    while (t < NTILES) {
        cp_wait_all();
        __syncthreads();                // buf[cur] ready; s_next[cur] visible

        int tn = s_next[cur];
        if (tn < NTILES) {
            load_tile_async(tbuf[cur ^ 1], wbuf[cur ^ 1], tn, x);
            cp_commit();
        }
        if (tid == 0) s_next[cur ^ 1] = atomicAdd(&g_tile_counter, 1);

        // ---- compute tile t from buf[cur] ----
        int bc = t >> 2;
        int r0 = (t & 3) * STRIP;

        float w[KK];
        {
            const float4* wv = reinterpret_cast<const float4*>(wbuf[cur]);
            #pragma unroll
            for (int q = 0; q < 12; q++) {
                float4 f = wv[q];
                w[4 * q + 0] = f.x; w[4 * q + 1] = f.y;
                w[4 * q + 2] = f.z; w[4 * q + 3] = f.w;
            }
            w[48] = wbuf[cur][48];
        }

        float bia = __ldg(&bias[bc % DIM]);
        float acc[4][4];
        #pragma unroll
        for (int i = 0; i < 4; i++)
            #pragma unroll
            for (int j = 0; j < 4; j++) acc[i][j] = bia;

        const float* tile = tbuf[cur];
        #pragma unroll
        for (int ir = 0; ir < 4 + KS - 1; ir++) {     // 10 tile rows
            const float* tr = &tile[(rbase + ir) * TSTRIDE + col];
            float4 A = *reinterpret_cast<const float4*>(tr);
            float4 Bv = *reinterpret_cast<const float4*>(tr + 4);
            float4 Cv = *reinterpret_cast<const float4*>(tr + 8);
            float v[12] = {A.x, A.y, A.z, A.w,
                           Bv.x, Bv.y, Bv.z, Bv.w,
                           Cv.x, Cv.y, Cv.z, Cv.w};
            #pragma unroll
            for (int kh = 0; kh < KS; kh++) {
                int orr = ir - kh;
                if (orr >= 0 && orr < 4) {
                    #pragma unroll
                    for (int jj = 0; jj < 4; jj++) {
                        float s = acc[orr][jj];
                        #pragma unroll
                        for (int kw = 0; kw < KS; kw++)
                            s = fmaf(v[jj + kw + 1], w[kh * KS + kw], s);
                        acc[orr][jj] = s;
                    }
                }
            }
        }

        float* op = out + (size_t)bc * PLANE + (size_t)(r0 + rbase) * Ww + col;
        #pragma unroll
        for (int orr = 0; orr < 4; orr++)
            *reinterpret_cast<float4*>(op + (size_t)orr * Ww) =
                make_float4(acc[orr][0], acc[orr][1], acc[orr][2], acc[orr][3]);

        t = tn;
        cur ^= 1;
    }
}

// ============================================================
// launch
// inputs: 0:x 1:w1 2:bn_gamma 3:bn_beta 4:bn_mean 5:bn_var 6:w2 7:b2 8:bias
// ============================================================
extern "C" void kernel_launch(void* const* d_in, const int* in_sizes, int n_in,
                              void* d_out, int out_size) {
    const float* x     = (const float*)d_in[0];
    const float* w1    = (const float*)d_in[1];
    const float* gamma = (const float*)d_in[2];
    const float* beta  = (const float*)d_in[3];
    const float* mean  = (const float*)d_in[4];
    const float* var   = (const float*)d_in[5];
    const float* w2    = (const float*)d_in[6];
    const float* b2    = (const float*)d_in[7];
    const float* bias  = (const float*)d_in[8];
    float* out = (float*)d_out;

    pool_kernel<<<B * DIM, 256>>>(x);
    dim3 g2((OUTW + W2_CHUNK - 1) / W2_CHUNK, B);
    gen_wdyn_kernel<<<g2, 128>>>(w1, gamma, beta, mean, var, w2, b2);
    dwconv_kernel<<<DW_GRID, 256>>>(x, bias, out);
}